// round 15
// baseline (speedup 1.0000x reference)
#include <cuda_runtime.h>
#include <math.h>

#define WIDTH   128
#define HEIGHT  128
#define NPIX    (WIDTH * HEIGHT)
#define NEARP   0.1f
#define FARP    10.0f
#define EPSV    1e-8f

#define TILE_W   8
#define TILE_H   8
#define TILES_X  (WIDTH / TILE_W)                   // 16
#define NBLOCKS  ((WIDTH/TILE_W)*(HEIGHT/TILE_H))   // 256
#define NTHREADS 512
#define NWARPS   (NTHREADS / 32)                    // 16
#define PIXPB    (TILE_W * TILE_H)                  // 64
#define NSPLIT   (NTHREADS / PIXPB)                 // 8
#define VCAP     1024
#define FCAP     1024

struct Smem {
    float4 svd[VCAP];                 // x, y, z(NaN if invalid), 1/w
    float4 s0[FCAP];                  // e0x, e0y, bx, by
    float4 s1[FCAP];                  // e1x, e1y, cx, cy
    float4 s2[FCAP];                  // e2x, e2y, ax, ay
    float4 s3[FCAP];                  // za, zb, zc, inva
    int    slist[FCAP];
    unsigned long long mergebuf[NSPLIT - 1][PIXPB];
    float  sM[16];
    int    wtot[NWARPS];
    int    wbase[NWARPS];
    int    slen;
};

__device__ __forceinline__ float f_nan() { return __int_as_float(0x7fc00000); }

// --------- camera matrix (view @ proj) --------------------------------------
__device__ void compute_matrix(const float* camf, const float* camc,
                               const float* camt, const float* camrt,
                               float* M)
{
    float f   = 0.5f * (camf[0] + camf[1]);
    float ccx = camc[0], ccy = camc[1];
    float nf  = NEARP / f;
    float right = ((float)WIDTH - (ccx + 0.5f)) * nf;
    float left  = -(ccx + 0.5f) * nf;
    float top   = (ccy + 0.5f) * nf;
    float bot   = -((float)HEIGHT - ccy + 0.5f) * nf;
    float m[4][4];
    #pragma unroll
    for (int i = 0; i < 4; i++)
        #pragma unroll
        for (int j = 0; j < 4; j++) m[i][j] = 0.0f;
    m[0][0] = 2.0f * NEARP / (right - left); m[0][2] = (right + left) / (right - left);
    m[1][1] = 2.0f * NEARP / (top - bot);    m[1][2] = (top + bot) / (top - bot);
    m[2][2] = -(FARP + NEARP) / (FARP - NEARP);
    m[2][3] = -2.0f * FARP * NEARP / (FARP - NEARP);
    m[3][2] = -1.0f;
    float P[4][4];
    #pragma unroll
    for (int i = 0; i < 4; i++)
        #pragma unroll
        for (int j = 0; j < 4; j++) P[i][j] = m[j][i];

    float rx = camrt[0], ry = camrt[1], rz = camrt[2];
    float th = sqrtf(rx * rx + ry * ry + rz * rz + 1e-12f);
    float kx = rx / th, ky = ry / th, kz = rz / th;
    float s  = sinf(th);
    float cc = 1.0f - cosf(th);
    float K[3][3] = {{0.f, -kz, ky}, {kz, 0.f, -kx}, {-ky, kx, 0.f}};
    float K2[3][3];
    #pragma unroll
    for (int i = 0; i < 3; i++)
        #pragma unroll
        for (int j = 0; j < 3; j++) {
            float acc = 0.f;
            #pragma unroll
            for (int k = 0; k < 3; k++) acc += K[i][k] * K[k][j];
            K2[i][j] = acc;
        }
    float R[3][3];
    #pragma unroll
    for (int i = 0; i < 3; i++)
        #pragma unroll
        for (int j = 0; j < 3; j++)
            R[i][j] = (i == j ? 1.0f : 0.0f) + s * K[i][j] + cc * K2[i][j];

    float Vw[4][4];
    #pragma unroll
    for (int i = 0; i < 4; i++)
        #pragma unroll
        for (int j = 0; j < 4; j++) Vw[i][j] = 0.0f;
    #pragma unroll
    for (int i = 0; i < 3; i++)
        #pragma unroll
        for (int j = 0; j < 3; j++) Vw[i][j] = R[j][i];
    Vw[3][0] = camt[0]; Vw[3][1] = camt[1]; Vw[3][2] = camt[2];
    Vw[3][3] = 1.0f;

    #pragma unroll
    for (int i = 0; i < 4; i++)
        #pragma unroll
        for (int j = 0; j < 4; j++) {
            float acc = 0.f;
            #pragma unroll
            for (int k = 0; k < 4; k++) acc += Vw[i][k] * P[k][j];
            M[i * 4 + j] = acc;
        }
}

__device__ __forceinline__ float4 transform_vertex(const float* __restrict__ v,
                                                   int i, const float* __restrict__ M)
{
    float x = v[3 * i], y = v[3 * i + 1], z = v[3 * i + 2];
    float c0 = x * M[0] + y * M[4] + z * M[8]  + M[12];
    float c1 = x * M[1] + y * M[5] + z * M[9]  + M[13];
    float c2 = x * M[2] + y * M[6] + z * M[10] + M[14];
    float c3 = x * M[3] + y * M[7] + z * M[11] + M[15];
    bool valid = (c3 > EPSV);
    float ws = valid ? c3 : 1.0f;
    float nx = c0 / ws, ny = c1 / ws, nz = c2 / ws;
    float4 r;
    r.x = (nx * 0.5f + 0.5f) * (float)WIDTH;
    r.y = (0.5f - ny * 0.5f) * (float)HEIGHT;
    r.z = valid ? nz : f_nan();
    r.w = 1.0f / ws;
    return r;
}

// --------- the whole renderer in one kernel ---------------------------------
__global__ void __launch_bounds__(NTHREADS, 2)
render_kernel(const float* __restrict__ v,
              const float* __restrict__ vc,
              const int* __restrict__ f,
              const float* __restrict__ bg,
              const float* __restrict__ camf,
              const float* __restrict__ camc,
              const float* __restrict__ camt,
              const float* __restrict__ camrt,
              float* __restrict__ out,
              int V, int F)
{
    extern __shared__ char raw[];
    Smem* sm = (Smem*)raw;

    int tid  = threadIdx.x;
    int lane = tid & 31;
    int wid  = tid >> 5;

    if (tid == 0) compute_matrix(camf, camc, camt, camrt, sm->sM);
    __syncthreads();

    // ---- phase 1: vertices -> smem
    for (int i = tid; i < V; i += NTHREADS)
        sm->svd[i] = transform_vertex(v, i, sm->sM);
    __syncthreads();

    // ---- tile geometry
    int tile = blockIdx.x;
    int tx0 = (tile % TILES_X) * TILE_W;
    int ty0 = (tile / TILES_X) * TILE_H;
    float tileL = (float)tx0, tileR = (float)(tx0 + TILE_W);
    float tileT = (float)ty0, tileB = (float)(ty0 + TILE_H);
    float cxm = tileL + 0.5f * (float)TILE_W;
    float cym = tileT + 0.5f * (float)TILE_H;
    const float hw = 0.5f * (float)TILE_W;
    const float hh = 0.5f * (float)TILE_H;

    // ---- phase 2: ordered compaction (bbox + conservative edge cull)
    //      thread t owns tris [2t, 2t+2)
    int tbase = tid * 2;
    unsigned passbits = 0;
    int cnt = 0;
    #pragma unroll
    for (int j = 0; j < 2; j++) {
        int t = tbase + j;
        if (t < F) {
            int i0 = f[3 * t], i1 = f[3 * t + 1], i2 = f[3 * t + 2];
            float4 A = sm->svd[i0], B = sm->svd[i1], C = sm->svd[i2];
            float ax = A.x, ay = A.y, bx = B.x, by = B.y, cx = C.x, cy = C.y;
            float xmn = fminf(ax, fminf(bx, cx));
            float xmx = fmaxf(ax, fmaxf(bx, cx));
            float ymn = fminf(ay, fminf(by, cy));
            float ymx = fmaxf(ay, fmaxf(by, cy));
            // bbox reject (NaN coords -> all compares false -> kept; harmless)
            bool reject = (xmx < tileL) | (xmn > tileR) | (ymx < tileT) | (ymn > tileB);
            if (!reject) {
                // conservative half-plane cull: reject iff b_i < 0 provably
                // holds over the whole tile (linear bound + fp slack).
                float e0x = cx - bx, e0y = cy - by;
                float e1x = ax - cx, e1y = ay - cy;
                float e2x = bx - ax, e2y = by - ay;
                float area = e2x * (cy - ay) - e2y * (cx - ax);
                bool areaok = fabsf(area) > EPSV;
                float inva = 1.0f / (areaok ? area : 1.0f);
                float ai = fabsf(inva);
                float w0c = e0x * (cym - by) - e0y * (cxm - bx);
                float w1c = e1x * (cym - cy) - e1y * (cxm - cx);
                float w2c = e2x * (cym - ay) - e2y * (cxm - ax);
                float rb0 = (fabsf(e0y) * hw + fabsf(e0x) * hh) * ai * 1.001f + 1e-3f;
                float rb1 = (fabsf(e1y) * hw + fabsf(e1x) * hh) * ai * 1.001f + 1e-3f;
                float rb2 = (fabsf(e2y) * hw + fabsf(e2x) * hh) * ai * 1.001f + 1e-3f;
                float b0c = w0c * inva, b1c = w1c * inva, b2c = w2c * inva;
                // NaN -> compares false -> kept (safe)
                bool ereject = (b0c < -rb0) | (b1c < -rb1) | (b2c < -rb2);
                if (!ereject) { passbits |= (1u << j); cnt++; }
            }
        }
    }
    // block exclusive scan of cnt
    int x = cnt;
    #pragma unroll
    for (int o = 1; o < 32; o <<= 1) {
        int y = __shfl_up_sync(0xffffffffu, x, o);
        if (lane >= o) x += y;
    }
    if (lane == 31) sm->wtot[wid] = x;
    __syncthreads();
    if (tid == 0) {
        int s = 0;
        #pragma unroll
        for (int i = 0; i < NWARPS; i++) { sm->wbase[i] = s; s += sm->wtot[i]; }
        sm->slen = s;
    }
    __syncthreads();

    // ---- phase 2b: fused scatter + setup (no separate setup phase/barrier).
    //      Owner thread writes each surviving triangle's full setup record at
    //      its scanned slot; list remains ascending in triangle index.
    int o = sm->wbase[wid] + x - cnt;   // exclusive offset, order preserved
    #pragma unroll
    for (int j = 0; j < 2; j++) {
        if (passbits & (1u << j)) {
            int t = tbase + j;
            int i0 = f[3 * t], i1 = f[3 * t + 1], i2 = f[3 * t + 2];
            float4 A = sm->svd[i0], Bv = sm->svd[i1], C = sm->svd[i2];
            float ax = A.x, ay = A.y, bx = Bv.x, by = Bv.y, cx = C.x, cy = C.y;
            float e0x = cx - bx, e0y = cy - by;
            float e1x = ax - cx, e1y = ay - cy;
            float e2x = bx - ax, e2y = by - ay;
            float area = e2x * (cy - ay) - e2y * (cx - ax);
            bool areaok = fabsf(area) > EPSV;
            float inva = 1.0f / (areaok ? area : 1.0f);
            float za = A.z, zb = Bv.z, zc = C.z;   // NaN if vert invalid
            if (!areaok) za = f_nan();
            sm->s0[o] = make_float4(e0x, e0y, bx, by);
            sm->s1[o] = make_float4(e1x, e1y, cx, cy);
            sm->s2[o] = make_float4(e2x, e2y, ax, ay);
            sm->s3[o] = make_float4(za, zb, zc, inva);
            sm->slist[o] = t;
            o++;
        }
    }
    __syncthreads();

    int listlen = sm->slen;

    // ---- phase 4: raster. tid&63 = pixel, tid>>6 = list segment (0..7)
    int pix = tid & (PIXPB - 1);
    int seg = tid >> 6;
    int pxi = tx0 + (pix % TILE_W);
    int pyi = ty0 + (pix / TILE_W);
    float px = (float)pxi + 0.5f;
    float py = (float)pyi + 0.5f;

    int qlen = (listlen + NSPLIT - 1) / NSPLIT;
    int lo = seg * qlen;
    int hi = lo + qlen; if (hi > listlen) hi = listlen;

    float bestz = 0.0f;
    int   bestk = -1;

    #pragma unroll 4
    for (int k = lo; k < hi; k++) {
        float4 q0 = sm->s0[k];
        float4 q1 = sm->s1[k];
        float4 q2 = sm->s2[k];
        float4 q3 = sm->s3[k];
        float w0 = q0.x * (py - q0.w) - q0.y * (px - q0.z); // E(b,c)
        float w1 = q1.x * (py - q1.w) - q1.y * (px - q1.z); // E(c,a)
        float w2 = q2.x * (py - q2.w) - q2.y * (px - q2.z); // E(a,b)
        float b0 = w0 * q3.w;
        float b1 = w1 * q3.w;
        float b2 = w2 * q3.w;
        float z  = b0 * q3.x + b1 * q3.y + b2 * q3.z;        // NaN if invalid
        bool inside = (b0 >= 0.0f) & (b1 >= 0.0f) & (b2 >= 0.0f) &
                      (z >= -1.0f) & (z <= 1.0f);
        if (inside && (bestk < 0 || z < bestz)) { bestz = z; bestk = k; }
    }

    // pack sortable key: (monotone depth << 32) | tri_index; empty = ~0
    // (slist ascending => lowest k == lowest tri index; argmin tie-break kept)
    unsigned long long key = ~0ull;
    if (bestk >= 0) {
        unsigned int d = __float_as_uint(bestz);
        d = (d & 0x80000000u) ? ~d : (d | 0x80000000u);
        key = ((unsigned long long)d << 32) | (unsigned int)sm->slist[bestk];
    }

    if (seg > 0) sm->mergebuf[seg - 1][pix] = key;
    __syncthreads();

    // ---- phase 5: merge + shade (segment-0 threads)
    if (seg == 0) {
        #pragma unroll
        for (int s = 0; s < NSPLIT - 1; s++) {
            unsigned long long kb = sm->mergebuf[s][pix];
            if (kb < key) key = kb;
        }

        float r, g, bl;
        if (key != ~0ull) {
            int t = (int)(unsigned int)(key & 0xffffffffu);
            int i0 = f[3 * t], i1 = f[3 * t + 1], i2 = f[3 * t + 2];
            float4 A = sm->svd[i0], Bv = sm->svd[i1], C = sm->svd[i2];
            float ax = A.x, ay = A.y, bx = Bv.x, by = Bv.y, cx = C.x, cy = C.y;
            float w0 = (cx - bx) * (py - by) - (cy - by) * (px - bx);
            float w1 = (ax - cx) * (py - cy) - (ay - cy) * (px - cx);
            float w2 = (bx - ax) * (py - ay) - (by - ay) * (px - ax);
            float area = (bx - ax) * (cy - ay) - (by - ay) * (cx - ax);
            bool areaok = fabsf(area) > EPSV;
            float inva = 1.0f / (areaok ? area : 1.0f);
            float b0 = w0 * inva;
            float b1 = w1 * inva;
            float b2 = w2 * inva;
            float g0 = b0 * A.w, g1 = b1 * Bv.w, g2 = b2 * C.w;
            float den = g0 + g1 + g2;
            den = (fabsf(den) > EPSV) ? den : 1.0f;
            r  = (g0 * vc[3 * i0 + 0] + g1 * vc[3 * i1 + 0] + g2 * vc[3 * i2 + 0]) / den;
            g  = (g0 * vc[3 * i0 + 1] + g1 * vc[3 * i1 + 1] + g2 * vc[3 * i2 + 1]) / den;
            bl = (g0 * vc[3 * i0 + 2] + g1 * vc[3 * i1 + 2] + g2 * vc[3 * i2 + 2]) / den;
        } else {
            r = bg[0]; g = bg[1]; bl = bg[2];
        }
        int p = pyi * WIDTH + pxi;
        out[3 * p + 0] = r;
        out[3 * p + 1] = g;
        out[3 * p + 2] = bl;
    }
}

// --------- launch -----------------------------------------------------------
extern "C" void kernel_launch(void* const* d_in, const int* in_sizes, int n_in,
                              void* d_out, int out_size)
{
    const float* v     = (const float*)d_in[0];
    const float* vc    = (const float*)d_in[1];
    const int*   f     = (const int*)  d_in[2];
    const float* bg    = (const float*)d_in[3];
    const float* camf  = (const float*)d_in[4];
    const float* camc  = (const float*)d_in[5];
    const float* camt  = (const float*)d_in[6];
    const float* camrt = (const float*)d_in[7];

    int B = out_size / (NPIX * 3);
    int V = in_sizes[1] / 3;
    int F = in_sizes[2] / 3;
    if (V > VCAP) V = VCAP;
    if (F > FCAP) F = FCAP;

    cudaFuncSetAttribute(render_kernel,
                         cudaFuncAttributeMaxDynamicSharedMemorySize,
                         (int)sizeof(Smem));

    for (int b = 0; b < B; b++) {
        render_kernel<<<NBLOCKS, NTHREADS, sizeof(Smem)>>>(
            v + (size_t)b * V * 3, vc, f, bg, camf, camc, camt, camrt,
            (float*)d_out + (size_t)b * NPIX * 3, V, F);
    }
}

// round 16
// speedup vs baseline: 1.0388x; 1.0388x over previous
#include <cuda_runtime.h>
#include <math.h>

#define WIDTH   128
#define HEIGHT  128
#define NPIX    (WIDTH * HEIGHT)
#define NEARP   0.1f
#define FARP    10.0f
#define EPSV    1e-8f

#define TILE_W   8
#define TILE_H   8
#define TILES_X  (WIDTH / TILE_W)                   // 16
#define NBLOCKS  ((WIDTH/TILE_W)*(HEIGHT/TILE_H))   // 256
#define NTHREADS 512
#define NWARPS   (NTHREADS / 32)                    // 16
#define PIXPB    (TILE_W * TILE_H)                  // 64
#define NSPLIT   (NTHREADS / PIXPB)                 // 8
#define VCAP     1024
#define FCAP     1024

struct Smem {
    float4 svd[VCAP];                 // x, y, z(NaN if invalid), 1/w
    float  svc[VCAP * 3];             // vertex colors (preloaded)
    float4 s0[FCAP];                  // e0x, e0y, bx, by
    float4 s1[FCAP];                  // e1x, e1y, cx, cy
    float4 s2[FCAP];                  // e2x, e2y, ax, ay
    float4 s3[FCAP];                  // za, zb, zc, inva
    int    slist[FCAP];
    unsigned long long mergebuf[NSPLIT - 1][PIXPB];
    float  sM[16];
    int    wtot[NWARPS];
    int    wbase[NWARPS];
    int    slen;
};

__device__ __forceinline__ float f_nan() { return __int_as_float(0x7fc00000); }

// --------- camera matrix (view @ proj) --------------------------------------
__device__ void compute_matrix(const float* camf, const float* camc,
                               const float* camt, const float* camrt,
                               float* M)
{
    float f   = 0.5f * (camf[0] + camf[1]);
    float ccx = camc[0], ccy = camc[1];
    float nf  = NEARP / f;
    float right = ((float)WIDTH - (ccx + 0.5f)) * nf;
    float left  = -(ccx + 0.5f) * nf;
    float top   = (ccy + 0.5f) * nf;
    float bot   = -((float)HEIGHT - ccy + 0.5f) * nf;
    float m[4][4];
    #pragma unroll
    for (int i = 0; i < 4; i++)
        #pragma unroll
        for (int j = 0; j < 4; j++) m[i][j] = 0.0f;
    m[0][0] = 2.0f * NEARP / (right - left); m[0][2] = (right + left) / (right - left);
    m[1][1] = 2.0f * NEARP / (top - bot);    m[1][2] = (top + bot) / (top - bot);
    m[2][2] = -(FARP + NEARP) / (FARP - NEARP);
    m[2][3] = -2.0f * FARP * NEARP / (FARP - NEARP);
    m[3][2] = -1.0f;
    float P[4][4];
    #pragma unroll
    for (int i = 0; i < 4; i++)
        #pragma unroll
        for (int j = 0; j < 4; j++) P[i][j] = m[j][i];

    float rx = camrt[0], ry = camrt[1], rz = camrt[2];
    float th = sqrtf(rx * rx + ry * ry + rz * rz + 1e-12f);
    float kx = rx / th, ky = ry / th, kz = rz / th;
    float s  = sinf(th);
    float cc = 1.0f - cosf(th);
    float K[3][3] = {{0.f, -kz, ky}, {kz, 0.f, -kx}, {-ky, kx, 0.f}};
    float K2[3][3];
    #pragma unroll
    for (int i = 0; i < 3; i++)
        #pragma unroll
        for (int j = 0; j < 3; j++) {
            float acc = 0.f;
            #pragma unroll
            for (int k = 0; k < 3; k++) acc += K[i][k] * K[k][j];
            K2[i][j] = acc;
        }
    float R[3][3];
    #pragma unroll
    for (int i = 0; i < 3; i++)
        #pragma unroll
        for (int j = 0; j < 3; j++)
            R[i][j] = (i == j ? 1.0f : 0.0f) + s * K[i][j] + cc * K2[i][j];

    float Vw[4][4];
    #pragma unroll
    for (int i = 0; i < 4; i++)
        #pragma unroll
        for (int j = 0; j < 4; j++) Vw[i][j] = 0.0f;
    #pragma unroll
    for (int i = 0; i < 3; i++)
        #pragma unroll
        for (int j = 0; j < 3; j++) Vw[i][j] = R[j][i];
    Vw[3][0] = camt[0]; Vw[3][1] = camt[1]; Vw[3][2] = camt[2];
    Vw[3][3] = 1.0f;

    #pragma unroll
    for (int i = 0; i < 4; i++)
        #pragma unroll
        for (int j = 0; j < 4; j++) {
            float acc = 0.f;
            #pragma unroll
            for (int k = 0; k < 4; k++) acc += Vw[i][k] * P[k][j];
            M[i * 4 + j] = acc;
        }
}

__device__ __forceinline__ float4 transform_vertex(const float* __restrict__ v,
                                                   int i, const float* __restrict__ M)
{
    float x = v[3 * i], y = v[3 * i + 1], z = v[3 * i + 2];
    float c0 = x * M[0] + y * M[4] + z * M[8]  + M[12];
    float c1 = x * M[1] + y * M[5] + z * M[9]  + M[13];
    float c2 = x * M[2] + y * M[6] + z * M[10] + M[14];
    float c3 = x * M[3] + y * M[7] + z * M[11] + M[15];
    bool valid = (c3 > EPSV);
    float ws = valid ? c3 : 1.0f;
    float nx = c0 / ws, ny = c1 / ws, nz = c2 / ws;
    float4 r;
    r.x = (nx * 0.5f + 0.5f) * (float)WIDTH;
    r.y = (0.5f - ny * 0.5f) * (float)HEIGHT;
    r.z = valid ? nz : f_nan();
    r.w = 1.0f / ws;
    return r;
}

// --------- the whole renderer in one kernel ---------------------------------
__global__ void __launch_bounds__(NTHREADS, 2)
render_kernel(const float* __restrict__ v,
              const float* __restrict__ vc,
              const int* __restrict__ f,
              const float* __restrict__ bg,
              const float* __restrict__ camf,
              const float* __restrict__ camc,
              const float* __restrict__ camt,
              const float* __restrict__ camrt,
              float* __restrict__ out,
              int V, int F)
{
    extern __shared__ char raw[];
    Smem* sm = (Smem*)raw;

    int tid  = threadIdx.x;
    int lane = tid & 31;
    int wid  = tid >> 5;

    if (tid == 0) compute_matrix(camf, camc, camt, camrt, sm->sM);
    __syncthreads();

    // ---- phase 1: vertices + colors -> smem (color preload hides behind
    //      the transform's division latency)
    for (int i = tid; i < V; i += NTHREADS)
        sm->svd[i] = transform_vertex(v, i, sm->sM);
    for (int i = tid; i < V * 3; i += NTHREADS)
        sm->svc[i] = vc[i];
    __syncthreads();

    // ---- tile geometry
    int tile = blockIdx.x;
    int tx0 = (tile % TILES_X) * TILE_W;
    int ty0 = (tile / TILES_X) * TILE_H;
    float tileL = (float)tx0, tileR = (float)(tx0 + TILE_W);
    float tileT = (float)ty0, tileB = (float)(ty0 + TILE_H);
    float cxm = tileL + 0.5f * (float)TILE_W;
    float cym = tileT + 0.5f * (float)TILE_H;
    const float hw = 0.5f * (float)TILE_W;
    const float hh = 0.5f * (float)TILE_H;

    // ---- phase 2: ordered compaction (bbox + division-free conservative
    //      edge cull). thread t owns tris [2t, 2t+2)
    int tbase = tid * 2;
    unsigned passbits = 0;
    int cnt = 0;
    #pragma unroll
    for (int j = 0; j < 2; j++) {
        int t = tbase + j;
        if (t < F) {
            int i0 = f[3 * t], i1 = f[3 * t + 1], i2 = f[3 * t + 2];
            float4 A = sm->svd[i0], B = sm->svd[i1], C = sm->svd[i2];
            float ax = A.x, ay = A.y, bx = B.x, by = B.y, cx = C.x, cy = C.y;
            float xmn = fminf(ax, fminf(bx, cx));
            float xmx = fmaxf(ax, fmaxf(bx, cx));
            float ymn = fminf(ay, fminf(by, cy));
            float ymx = fmaxf(ay, fmaxf(by, cy));
            // bbox reject (NaN coords -> all compares false -> kept; harmless)
            bool reject = (xmx < tileL) | (xmn > tileR) | (ymx < tileT) | (ymn > tileB);
            if (!reject) {
                // conservative half-plane cull in w-space (no division):
                // reject iff sign(area)*w_i(center) provably < 0 over the
                // whole tile: |w_i| varies by at most rw_i, plus fp slack
                // 1e-3*|area| (the old 1e-3 b-space slack scaled by area).
                float e0x = cx - bx, e0y = cy - by;
                float e1x = ax - cx, e1y = ay - cy;
                float e2x = bx - ax, e2y = by - ay;
                float area = e2x * (cy - ay) - e2y * (cx - ax);
                float sa = (area >= 0.0f) ? 1.0f : -1.0f;   // NaN -> -1 (safe)
                float slack = 1e-3f * fabsf(area);
                float w0c = e0x * (cym - by) - e0y * (cxm - bx);
                float w1c = e1x * (cym - cy) - e1y * (cxm - cx);
                float w2c = e2x * (cym - ay) - e2y * (cxm - ax);
                float rw0 = (fabsf(e0y) * hw + fabsf(e0x) * hh) * 1.001f + slack;
                float rw1 = (fabsf(e1y) * hw + fabsf(e1x) * hh) * 1.001f + slack;
                float rw2 = (fabsf(e2y) * hw + fabsf(e2x) * hh) * 1.001f + slack;
                // NaN -> compares false -> kept (safe; dies at z NaN later)
                bool ereject = (w0c * sa < -rw0) | (w1c * sa < -rw1) | (w2c * sa < -rw2);
                if (!ereject) { passbits |= (1u << j); cnt++; }
            }
        }
    }
    // block exclusive scan of cnt
    int x = cnt;
    #pragma unroll
    for (int o = 1; o < 32; o <<= 1) {
        int y = __shfl_up_sync(0xffffffffu, x, o);
        if (lane >= o) x += y;
    }
    if (lane == 31) sm->wtot[wid] = x;
    __syncthreads();
    if (tid == 0) {
        int s = 0;
        #pragma unroll
        for (int i = 0; i < NWARPS; i++) { sm->wbase[i] = s; s += sm->wtot[i]; }
        sm->slen = s;
    }
    __syncthreads();
    int o = sm->wbase[wid] + x - cnt;   // exclusive offset, order preserved
    #pragma unroll
    for (int j = 0; j < 2; j++)
        if (passbits & (1u << j)) sm->slist[o++] = tbase + j;
    __syncthreads();

    int listlen = sm->slen;

    // ---- phase 3: setup surviving triangles (coalesced; same fp forms)
    for (int k = tid; k < listlen; k += NTHREADS) {
        int t = sm->slist[k];
        int i0 = f[3 * t], i1 = f[3 * t + 1], i2 = f[3 * t + 2];
        float4 A = sm->svd[i0], Bv = sm->svd[i1], C = sm->svd[i2];
        float ax = A.x, ay = A.y, bx = Bv.x, by = Bv.y, cx = C.x, cy = C.y;
        float e0x = cx - bx, e0y = cy - by;
        float e1x = ax - cx, e1y = ay - cy;
        float e2x = bx - ax, e2y = by - ay;
        float area = e2x * (cy - ay) - e2y * (cx - ax);
        bool areaok = fabsf(area) > EPSV;
        float inva = 1.0f / (areaok ? area : 1.0f);
        float za = A.z, zb = Bv.z, zc = C.z;   // NaN if vert invalid
        if (!areaok) za = f_nan();
        sm->s0[k] = make_float4(e0x, e0y, bx, by);
        sm->s1[k] = make_float4(e1x, e1y, cx, cy);
        sm->s2[k] = make_float4(e2x, e2y, ax, ay);
        sm->s3[k] = make_float4(za, zb, zc, inva);
    }
    __syncthreads();

    // ---- phase 4: raster. tid&63 = pixel, tid>>6 = list segment (0..7)
    int pix = tid & (PIXPB - 1);
    int seg = tid >> 6;
    int pxi = tx0 + (pix % TILE_W);
    int pyi = ty0 + (pix / TILE_W);
    float px = (float)pxi + 0.5f;
    float py = (float)pyi + 0.5f;

    int qlen = (listlen + NSPLIT - 1) / NSPLIT;
    int lo = seg * qlen;
    int hi = lo + qlen; if (hi > listlen) hi = listlen;

    float bestz = 0.0f;
    int   bestk = -1;

    #pragma unroll 4
    for (int k = lo; k < hi; k++) {
        float4 q0 = sm->s0[k];
        float4 q1 = sm->s1[k];
        float4 q2 = sm->s2[k];
        float4 q3 = sm->s3[k];
        float w0 = q0.x * (py - q0.w) - q0.y * (px - q0.z); // E(b,c)
        float w1 = q1.x * (py - q1.w) - q1.y * (px - q1.z); // E(c,a)
        float w2 = q2.x * (py - q2.w) - q2.y * (px - q2.z); // E(a,b)
        float b0 = w0 * q3.w;
        float b1 = w1 * q3.w;
        float b2 = w2 * q3.w;
        float z  = b0 * q3.x + b1 * q3.y + b2 * q3.z;        // NaN if invalid
        bool inside = (b0 >= 0.0f) & (b1 >= 0.0f) & (b2 >= 0.0f) &
                      (z >= -1.0f) & (z <= 1.0f);
        if (inside && (bestk < 0 || z < bestz)) { bestz = z; bestk = k; }
    }

    // pack sortable key: (monotone depth << 32) | tri_index; empty = ~0
    // (slist ascending => lowest k == lowest tri index; argmin tie-break kept)
    unsigned long long key = ~0ull;
    if (bestk >= 0) {
        unsigned int d = __float_as_uint(bestz);
        d = (d & 0x80000000u) ? ~d : (d | 0x80000000u);
        key = ((unsigned long long)d << 32) | (unsigned int)sm->slist[bestk];
    }

    if (seg > 0) sm->mergebuf[seg - 1][pix] = key;
    __syncthreads();

    // ---- phase 5: merge + shade (segment-0 threads; colors from smem)
    if (seg == 0) {
        #pragma unroll
        for (int s = 0; s < NSPLIT - 1; s++) {
            unsigned long long kb = sm->mergebuf[s][pix];
            if (kb < key) key = kb;
        }

        float r, g, bl;
        if (key != ~0ull) {
            int t = (int)(unsigned int)(key & 0xffffffffu);
            int i0 = f[3 * t], i1 = f[3 * t + 1], i2 = f[3 * t + 2];
            float4 A = sm->svd[i0], Bv = sm->svd[i1], C = sm->svd[i2];
            float ax = A.x, ay = A.y, bx = Bv.x, by = Bv.y, cx = C.x, cy = C.y;
            float w0 = (cx - bx) * (py - by) - (cy - by) * (px - bx);
            float w1 = (ax - cx) * (py - cy) - (ay - cy) * (px - cx);
            float w2 = (bx - ax) * (py - ay) - (by - ay) * (px - ax);
            float area = (bx - ax) * (cy - ay) - (by - ay) * (cx - ax);
            bool areaok = fabsf(area) > EPSV;
            float inva = 1.0f / (areaok ? area : 1.0f);
            float b0 = w0 * inva;
            float b1 = w1 * inva;
            float b2 = w2 * inva;
            float g0 = b0 * A.w, g1 = b1 * Bv.w, g2 = b2 * C.w;
            float den = g0 + g1 + g2;
            den = (fabsf(den) > EPSV) ? den : 1.0f;
            r  = (g0 * sm->svc[3 * i0 + 0] + g1 * sm->svc[3 * i1 + 0] + g2 * sm->svc[3 * i2 + 0]) / den;
            g  = (g0 * sm->svc[3 * i0 + 1] + g1 * sm->svc[3 * i1 + 1] + g2 * sm->svc[3 * i2 + 1]) / den;
            bl = (g0 * sm->svc[3 * i0 + 2] + g1 * sm->svc[3 * i1 + 2] + g2 * sm->svc[3 * i2 + 2]) / den;
        } else {
            r = bg[0]; g = bg[1]; bl = bg[2];
        }
        int p = pyi * WIDTH + pxi;
        out[3 * p + 0] = r;
        out[3 * p + 1] = g;
        out[3 * p + 2] = bl;
    }
}

// --------- launch -----------------------------------------------------------
extern "C" void kernel_launch(void* const* d_in, const int* in_sizes, int n_in,
                              void* d_out, int out_size)
{
    const float* v     = (const float*)d_in[0];
    const float* vc    = (const float*)d_in[1];
    const int*   f     = (const int*)  d_in[2];
    const float* bg    = (const float*)d_in[3];
    const float* camf  = (const float*)d_in[4];
    const float* camc  = (const float*)d_in[5];
    const float* camt  = (const float*)d_in[6];
    const float* camrt = (const float*)d_in[7];

    int B = out_size / (NPIX * 3);
    int V = in_sizes[1] / 3;
    int F = in_sizes[2] / 3;
    if (V > VCAP) V = VCAP;
    if (F > FCAP) F = FCAP;

    cudaFuncSetAttribute(render_kernel,
                         cudaFuncAttributeMaxDynamicSharedMemorySize,
                         (int)sizeof(Smem));

    for (int b = 0; b < B; b++) {
        render_kernel<<<NBLOCKS, NTHREADS, sizeof(Smem)>>>(
            v + (size_t)b * V * 3, vc, f, bg, camf, camc, camt, camrt,
            (float*)d_out + (size_t)b * NPIX * 3, V, F);
    }
}

// round 17
// speedup vs baseline: 1.1577x; 1.1145x over previous
#include <cuda_runtime.h>
#include <math.h>

#define WIDTH   128
#define HEIGHT  128
#define NPIX    (WIDTH * HEIGHT)
#define NEARP   0.1f
#define FARP    10.0f
#define EPSV    1e-8f

#define TILE_W   8
#define TILE_H   8
#define TILES_X  (WIDTH / TILE_W)                   // 16
#define NBLOCKS  ((WIDTH/TILE_W)*(HEIGHT/TILE_H))   // 256
#define NTHREADS 512
#define NWARPS   (NTHREADS / 32)                    // 16
#define PIXPB    (TILE_W * TILE_H)                  // 64
#define NSPLIT   (NTHREADS / PIXPB)                 // 8
#define VCAP     1024
#define FCAP     1024

struct Smem {
    float4 svd[VCAP];                 // x, y, z(NaN if invalid), 1/w
    float4 s0[FCAP];                  // e0x, e0y, bx, by
    float4 s1[FCAP];                  // e1x, e1y, cx, cy
    float4 s2[FCAP];                  // e2x, e2y, ax, ay
    float4 s3[FCAP];                  // za, zb, zc, inva
    int    slist[FCAP];
    unsigned long long mergebuf[NSPLIT - 1][PIXPB];
    float  sM[16];
    int    wtot[NWARPS];
    int    wbase[NWARPS];
    int    slen;
};

__device__ __forceinline__ float f_nan() { return __int_as_float(0x7fc00000); }

// --------- camera matrix (view @ proj) --------------------------------------
__device__ void compute_matrix(const float* camf, const float* camc,
                               const float* camt, const float* camrt,
                               float* M)
{
    float f   = 0.5f * (camf[0] + camf[1]);
    float ccx = camc[0], ccy = camc[1];
    float nf  = NEARP / f;
    float right = ((float)WIDTH - (ccx + 0.5f)) * nf;
    float left  = -(ccx + 0.5f) * nf;
    float top   = (ccy + 0.5f) * nf;
    float bot   = -((float)HEIGHT - ccy + 0.5f) * nf;
    float m[4][4];
    #pragma unroll
    for (int i = 0; i < 4; i++)
        #pragma unroll
        for (int j = 0; j < 4; j++) m[i][j] = 0.0f;
    m[0][0] = 2.0f * NEARP / (right - left); m[0][2] = (right + left) / (right - left);
    m[1][1] = 2.0f * NEARP / (top - bot);    m[1][2] = (top + bot) / (top - bot);
    m[2][2] = -(FARP + NEARP) / (FARP - NEARP);
    m[2][3] = -2.0f * FARP * NEARP / (FARP - NEARP);
    m[3][2] = -1.0f;
    float P[4][4];
    #pragma unroll
    for (int i = 0; i < 4; i++)
        #pragma unroll
        for (int j = 0; j < 4; j++) P[i][j] = m[j][i];

    float rx = camrt[0], ry = camrt[1], rz = camrt[2];
    float th = sqrtf(rx * rx + ry * ry + rz * rz + 1e-12f);
    float kx = rx / th, ky = ry / th, kz = rz / th;
    float s  = sinf(th);
    float cc = 1.0f - cosf(th);
    float K[3][3] = {{0.f, -kz, ky}, {kz, 0.f, -kx}, {-ky, kx, 0.f}};
    float K2[3][3];
    #pragma unroll
    for (int i = 0; i < 3; i++)
        #pragma unroll
        for (int j = 0; j < 3; j++) {
            float acc = 0.f;
            #pragma unroll
            for (int k = 0; k < 3; k++) acc += K[i][k] * K[k][j];
            K2[i][j] = acc;
        }
    float R[3][3];
    #pragma unroll
    for (int i = 0; i < 3; i++)
        #pragma unroll
        for (int j = 0; j < 3; j++)
            R[i][j] = (i == j ? 1.0f : 0.0f) + s * K[i][j] + cc * K2[i][j];

    float Vw[4][4];
    #pragma unroll
    for (int i = 0; i < 4; i++)
        #pragma unroll
        for (int j = 0; j < 4; j++) Vw[i][j] = 0.0f;
    #pragma unroll
    for (int i = 0; i < 3; i++)
        #pragma unroll
        for (int j = 0; j < 3; j++) Vw[i][j] = R[j][i];
    Vw[3][0] = camt[0]; Vw[3][1] = camt[1]; Vw[3][2] = camt[2];
    Vw[3][3] = 1.0f;

    #pragma unroll
    for (int i = 0; i < 4; i++)
        #pragma unroll
        for (int j = 0; j < 4; j++) {
            float acc = 0.f;
            #pragma unroll
            for (int k = 0; k < 4; k++) acc += Vw[i][k] * P[k][j];
            M[i * 4 + j] = acc;
        }
}

__device__ __forceinline__ float4 transform_vertex(const float* __restrict__ v,
                                                   int i, const float* __restrict__ M)
{
    float x = v[3 * i], y = v[3 * i + 1], z = v[3 * i + 2];
    float c0 = x * M[0] + y * M[4] + z * M[8]  + M[12];
    float c1 = x * M[1] + y * M[5] + z * M[9]  + M[13];
    float c2 = x * M[2] + y * M[6] + z * M[10] + M[14];
    float c3 = x * M[3] + y * M[7] + z * M[11] + M[15];
    bool valid = (c3 > EPSV);
    float ws = valid ? c3 : 1.0f;
    float nx = c0 / ws, ny = c1 / ws, nz = c2 / ws;
    float4 r;
    r.x = (nx * 0.5f + 0.5f) * (float)WIDTH;
    r.y = (0.5f - ny * 0.5f) * (float)HEIGHT;
    r.z = valid ? nz : f_nan();
    r.w = 1.0f / ws;
    return r;
}

// --------- the whole renderer in one kernel ---------------------------------
__global__ void __launch_bounds__(NTHREADS, 2)
render_kernel(const float* __restrict__ v,
              const float* __restrict__ vc,
              const int* __restrict__ f,
              const float* __restrict__ bg,
              const float* __restrict__ camf,
              const float* __restrict__ camc,
              const float* __restrict__ camt,
              const float* __restrict__ camrt,
              float* __restrict__ out,
              int V, int F)
{
    extern __shared__ char raw[];
    Smem* sm = (Smem*)raw;

    int tid  = threadIdx.x;
    int lane = tid & 31;
    int wid  = tid >> 5;

    if (tid == 0) compute_matrix(camf, camc, camt, camrt, sm->sM);
    __syncthreads();

    // ---- phase 1: vertices -> smem
    for (int i = tid; i < V; i += NTHREADS)
        sm->svd[i] = transform_vertex(v, i, sm->sM);
    __syncthreads();

    // ---- tile geometry
    int tile = blockIdx.x;
    int tx0 = (tile % TILES_X) * TILE_W;
    int ty0 = (tile / TILES_X) * TILE_H;
    float tileL = (float)tx0, tileR = (float)(tx0 + TILE_W);
    float tileT = (float)ty0, tileB = (float)(ty0 + TILE_H);
    float cxm = tileL + 0.5f * (float)TILE_W;
    float cym = tileT + 0.5f * (float)TILE_H;
    const float hw = 0.5f * (float)TILE_W;
    const float hh = 0.5f * (float)TILE_H;

    // ---- phase 2: ordered compaction (bbox + division-free conservative
    //      edge cull). thread t owns tris [2t, 2t+2)
    int tbase = tid * 2;
    unsigned passbits = 0;
    int cnt = 0;
    #pragma unroll
    for (int j = 0; j < 2; j++) {
        int t = tbase + j;
        if (t < F) {
            int i0 = f[3 * t], i1 = f[3 * t + 1], i2 = f[3 * t + 2];
            float4 A = sm->svd[i0], B = sm->svd[i1], C = sm->svd[i2];
            float ax = A.x, ay = A.y, bx = B.x, by = B.y, cx = C.x, cy = C.y;
            float xmn = fminf(ax, fminf(bx, cx));
            float xmx = fmaxf(ax, fmaxf(bx, cx));
            float ymn = fminf(ay, fminf(by, cy));
            float ymx = fmaxf(ay, fmaxf(by, cy));
            // bbox reject (NaN coords -> all compares false -> kept; harmless)
            bool reject = (xmx < tileL) | (xmn > tileR) | (ymx < tileT) | (ymn > tileB);
            if (!reject) {
                // conservative half-plane cull in w-space (no division):
                // reject iff sign(area)*w_i(center) provably < 0 over the
                // whole tile (linear variation bound + fp slack scaled by
                // |area|, equivalent to the b-space test).
                float e0x = cx - bx, e0y = cy - by;
                float e1x = ax - cx, e1y = ay - cy;
                float e2x = bx - ax, e2y = by - ay;
                float area = e2x * (cy - ay) - e2y * (cx - ax);
                float sa = (area >= 0.0f) ? 1.0f : -1.0f;   // NaN -> -1 (safe)
                float slack = 1e-3f * fabsf(area);
                float w0c = e0x * (cym - by) - e0y * (cxm - bx);
                float w1c = e1x * (cym - cy) - e1y * (cxm - cx);
                float w2c = e2x * (cym - ay) - e2y * (cxm - ax);
                float rw0 = (fabsf(e0y) * hw + fabsf(e0x) * hh) * 1.001f + slack;
                float rw1 = (fabsf(e1y) * hw + fabsf(e1x) * hh) * 1.001f + slack;
                float rw2 = (fabsf(e2y) * hw + fabsf(e2x) * hh) * 1.001f + slack;
                // NaN -> compares false -> kept (safe; dies at z NaN later)
                bool ereject = (w0c * sa < -rw0) | (w1c * sa < -rw1) | (w2c * sa < -rw2);
                if (!ereject) { passbits |= (1u << j); cnt++; }
            }
        }
    }
    // block exclusive scan of cnt
    int x = cnt;
    #pragma unroll
    for (int o = 1; o < 32; o <<= 1) {
        int y = __shfl_up_sync(0xffffffffu, x, o);
        if (lane >= o) x += y;
    }
    if (lane == 31) sm->wtot[wid] = x;
    __syncthreads();
    if (tid == 0) {
        int s = 0;
        #pragma unroll
        for (int i = 0; i < NWARPS; i++) { sm->wbase[i] = s; s += sm->wtot[i]; }
        sm->slen = s;
    }
    __syncthreads();
    int o = sm->wbase[wid] + x - cnt;   // exclusive offset, order preserved
    #pragma unroll
    for (int j = 0; j < 2; j++)
        if (passbits & (1u << j)) sm->slist[o++] = tbase + j;
    __syncthreads();

    int listlen = sm->slen;

    // ---- phase 3: setup surviving triangles (coalesced; same fp forms)
    for (int k = tid; k < listlen; k += NTHREADS) {
        int t = sm->slist[k];
        int i0 = f[3 * t], i1 = f[3 * t + 1], i2 = f[3 * t + 2];
        float4 A = sm->svd[i0], Bv = sm->svd[i1], C = sm->svd[i2];
        float ax = A.x, ay = A.y, bx = Bv.x, by = Bv.y, cx = C.x, cy = C.y;
        float e0x = cx - bx, e0y = cy - by;
        float e1x = ax - cx, e1y = ay - cy;
        float e2x = bx - ax, e2y = by - ay;
        float area = e2x * (cy - ay) - e2y * (cx - ax);
        bool areaok = fabsf(area) > EPSV;
        float inva = 1.0f / (areaok ? area : 1.0f);
        float za = A.z, zb = Bv.z, zc = C.z;   // NaN if vert invalid
        if (!areaok) za = f_nan();
        sm->s0[k] = make_float4(e0x, e0y, bx, by);
        sm->s1[k] = make_float4(e1x, e1y, cx, cy);
        sm->s2[k] = make_float4(e2x, e2y, ax, ay);
        sm->s3[k] = make_float4(za, zb, zc, inva);
    }
    __syncthreads();

    // ---- phase 4: raster. tid&63 = pixel, tid>>6 = list segment (0..7)
    int pix = tid & (PIXPB - 1);
    int seg = tid >> 6;
    int pxi = tx0 + (pix % TILE_W);
    int pyi = ty0 + (pix / TILE_W);
    float px = (float)pxi + 0.5f;
    float py = (float)pyi + 0.5f;

    int qlen = (listlen + NSPLIT - 1) / NSPLIT;
    int lo = seg * qlen;
    int hi = lo + qlen; if (hi > listlen) hi = listlen;

    float bestz = 0.0f;
    int   bestk = -1;

    #pragma unroll 4
    for (int k = lo; k < hi; k++) {
        float4 q0 = sm->s0[k];
        float4 q1 = sm->s1[k];
        float4 q2 = sm->s2[k];
        float4 q3 = sm->s3[k];
        float w0 = q0.x * (py - q0.w) - q0.y * (px - q0.z); // E(b,c)
        float w1 = q1.x * (py - q1.w) - q1.y * (px - q1.z); // E(c,a)
        float w2 = q2.x * (py - q2.w) - q2.y * (px - q2.z); // E(a,b)
        float b0 = w0 * q3.w;
        float b1 = w1 * q3.w;
        float b2 = w2 * q3.w;
        float z  = b0 * q3.x + b1 * q3.y + b2 * q3.z;        // NaN if invalid
        bool inside = (b0 >= 0.0f) & (b1 >= 0.0f) & (b2 >= 0.0f) &
                      (z >= -1.0f) & (z <= 1.0f);
        if (inside && (bestk < 0 || z < bestz)) { bestz = z; bestk = k; }
    }

    // pack sortable key: (monotone depth << 32) | tri_index; empty = ~0
    // (slist ascending => lowest k == lowest tri index; argmin tie-break kept)
    unsigned long long key = ~0ull;
    if (bestk >= 0) {
        unsigned int d = __float_as_uint(bestz);
        d = (d & 0x80000000u) ? ~d : (d | 0x80000000u);
        key = ((unsigned long long)d << 32) | (unsigned int)sm->slist[bestk];
    }

    if (seg > 0) sm->mergebuf[seg - 1][pix] = key;
    __syncthreads();

    // ---- phase 5: merge + shade (segment-0 threads)
    if (seg == 0) {
        #pragma unroll
        for (int s = 0; s < NSPLIT - 1; s++) {
            unsigned long long kb = sm->mergebuf[s][pix];
            if (kb < key) key = kb;
        }

        float r, g, bl;
        if (key != ~0ull) {
            int t = (int)(unsigned int)(key & 0xffffffffu);
            int i0 = f[3 * t], i1 = f[3 * t + 1], i2 = f[3 * t + 2];
            float4 A = sm->svd[i0], Bv = sm->svd[i1], C = sm->svd[i2];
            float ax = A.x, ay = A.y, bx = Bv.x, by = Bv.y, cx = C.x, cy = C.y;
            float w0 = (cx - bx) * (py - by) - (cy - by) * (px - bx);
            float w1 = (ax - cx) * (py - cy) - (ay - cy) * (px - cx);
            float w2 = (bx - ax) * (py - ay) - (by - ay) * (px - ax);
            float area = (bx - ax) * (cy - ay) - (by - ay) * (cx - ax);
            bool areaok = fabsf(area) > EPSV;
            float inva = 1.0f / (areaok ? area : 1.0f);
            float b0 = w0 * inva;
            float b1 = w1 * inva;
            float b2 = w2 * inva;
            float g0 = b0 * A.w, g1 = b1 * Bv.w, g2 = b2 * C.w;
            float den = g0 + g1 + g2;
            den = (fabsf(den) > EPSV) ? den : 1.0f;
            r  = (g0 * vc[3 * i0 + 0] + g1 * vc[3 * i1 + 0] + g2 * vc[3 * i2 + 0]) / den;
            g  = (g0 * vc[3 * i0 + 1] + g1 * vc[3 * i1 + 1] + g2 * vc[3 * i2 + 1]) / den;
            bl = (g0 * vc[3 * i0 + 2] + g1 * vc[3 * i1 + 2] + g2 * vc[3 * i2 + 2]) / den;
        } else {
            r = bg[0]; g = bg[1]; bl = bg[2];
        }
        int p = pyi * WIDTH + pxi;
        out[3 * p + 0] = r;
        out[3 * p + 1] = g;
        out[3 * p + 2] = bl;
    }
}

// --------- launch -----------------------------------------------------------
extern "C" void kernel_launch(void* const* d_in, const int* in_sizes, int n_in,
                              void* d_out, int out_size)
{
    const float* v     = (const float*)d_in[0];
    const float* vc    = (const float*)d_in[1];
    const int*   f     = (const int*)  d_in[2];
    const float* bg    = (const float*)d_in[3];
    const float* camf  = (const float*)d_in[4];
    const float* camc  = (const float*)d_in[5];
    const float* camt  = (const float*)d_in[6];
    const float* camrt = (const float*)d_in[7];

    int B = out_size / (NPIX * 3);
    int V = in_sizes[1] / 3;
    int F = in_sizes[2] / 3;
    if (V > VCAP) V = VCAP;
    if (F > FCAP) F = FCAP;

    cudaFuncSetAttribute(render_kernel,
                         cudaFuncAttributeMaxDynamicSharedMemorySize,
                         (int)sizeof(Smem));

    for (int b = 0; b < B; b++) {
        render_kernel<<<NBLOCKS, NTHREADS, sizeof(Smem)>>>(
            v + (size_t)b * V * 3, vc, f, bg, camf, camc, camt, camrt,
            (float*)d_out + (size_t)b * NPIX * 3, V, F);
    }
}